// round 6
// baseline (speedup 1.0000x reference)
#include <cuda_runtime.h>
#include <math.h>

#define NN 100000
#define NB 5000
#define NE 3200000

// ---- device scratch (static __device__ arrays: the sanctioned scratch mechanism) ----
__device__ __align__(16) float g_h[NN * 16];    // padded h rows (slot 15 = 0)
__device__ __align__(16) float g_agg[NN * 16];  // padded agg accumulator
__device__ float g_b[NN * 19];
__device__ int   g_rows[NE];
__device__ int   g_cols[NE];
__device__ float g_norm[NE];
__device__ int   g_deg[NN];
__device__ float g_dinv[NN];
__device__ float g_d2[NN];
__device__ float g_sum;
__device__ int   g_is64;   // 1 if edges are int64, 0 if int32

// ---- kernel D: detect edge dtype (int64 vs int32) ----
// int64 values in [0,1e5): every odd 32-bit word (high half) == 0.
// int32 values: odd words are random node ids, ~never all zero.
__global__ void k_detect(const int* __restrict__ ewords) {
    int nonzero = 0;
    for (int i = 0; i < 64; i++) nonzero |= ewords[2 * i + 1];
    g_is64 = (nonzero == 0) ? 1 : 0;
}

// ---- kernel 0: init deg=1 (self loop), zero sum ----
__global__ void k_init() {
    int v = blockIdx.x * blockDim.x + threadIdx.x;
    if (v < NN) g_deg[v] = 1;
    if (v == 0) g_sum = 0.0f;
}

__device__ __forceinline__ int load_edge(const void* edges, int is64, long long idx) {
    if (is64) return (int)((const long long*)edges)[idx];
    return ((const int*)edges)[idx];
}

// ---- kernel 1: in-degree histogram over col ----
__global__ void k_deg(const void* __restrict__ edges) {
    int e = blockIdx.x * blockDim.x + threadIdx.x;
    if (e >= NE) return;
    int c = load_edge(edges, g_is64, (long long)NE + e);
    if ((unsigned)c < (unsigned)NN) atomicAdd(&g_deg[c], 1);
}

// ---- kernel 2: dinv / d2 ----
__global__ void k_dinv() {
    int v = blockIdx.x * blockDim.x + threadIdx.x;
    if (v >= NN) return;
    float d = (float)g_deg[v];
    g_dinv[v] = 1.0f / sqrtf(d);
    g_d2[v]   = 1.0f / d;
}

// ---- kernel 3: edge prep (int32 indices + fused norm) ----
__global__ void k_eprep(const void* __restrict__ edges) {
    int e = blockIdx.x * blockDim.x + threadIdx.x;
    if (e >= NE) return;
    int is64 = g_is64;
    int r = load_edge(edges, is64, e);
    int c = load_edge(edges, is64, (long long)NE + e);
    if ((unsigned)r >= (unsigned)NN) r = 0;
    if ((unsigned)c >= (unsigned)NN) c = 0;
    g_rows[e] = r;
    g_cols[e] = c;
    g_norm[e] = g_dinv[r] * g_dinv[c];
}

// ---- kernel 4: b = [x1|x2t] W4^T + b4 ; agg = x1 W1^T + b1 - bg ----
__global__ void k_ab(const float* __restrict__ x1, const float* __restrict__ x2,
                     const float* __restrict__ W4, const float* __restrict__ b4,
                     const float* __restrict__ W1, const float* __restrict__ b1,
                     const float* __restrict__ bg) {
    __shared__ float sW4[19 * 19], sb4[19], sW1[15 * 15], sb1[15], sbg[15];
    for (int i = threadIdx.x; i < 19 * 19; i += blockDim.x) sW4[i] = W4[i];
    for (int i = threadIdx.x; i < 15 * 15; i += blockDim.x) sW1[i] = W1[i];
    if (threadIdx.x < 19) sb4[threadIdx.x] = b4[threadIdx.x];
    if (threadIdx.x < 15) { sb1[threadIdx.x] = b1[threadIdx.x]; sbg[threadIdx.x] = bg[threadIdx.x]; }
    __syncthreads();

    int v = blockIdx.x * blockDim.x + threadIdx.x;
    if (v >= NN) return;

    float in[19];
    const float* x1r = x1 + (size_t)v * 15;
#pragma unroll
    for (int k = 0; k < 15; k++) in[k] = x1r[k];
    const float* x2r = x2 + (size_t)(v % NB) * 4;
#pragma unroll
    for (int k = 0; k < 4; k++) in[15 + k] = x2r[k];

    float* brow = g_b + (size_t)v * 19;
#pragma unroll
    for (int j = 0; j < 19; j++) {
        float acc = sb4[j];
#pragma unroll
        for (int k = 0; k < 19; k++) acc = fmaf(sW4[j * 19 + k], in[k], acc);
        brow[j] = acc;
    }

    float* arow = g_agg + (size_t)v * 16;
#pragma unroll
    for (int i = 0; i < 15; i++) {
        float acc = sb1[i] - sbg[i];
#pragma unroll
        for (int k = 0; k < 15; k++) acc = fmaf(sW1[i * 15 + k], in[k], acc);
        arow[i] = acc;
    }
    arow[15] = 0.0f;
    g_h[(size_t)v * 16 + 15] = 0.0f;
}

// ---- kernel H: a = relu(agg+bg); h = Wg [a;b]; agg := h * (1/deg) (self-loop term) ----
__global__ void k_H(const float* __restrict__ Wg, const float* __restrict__ bg) {
    __shared__ float sWg[15 * 34], sbg[15];
    for (int i = threadIdx.x; i < 15 * 34; i += blockDim.x) sWg[i] = Wg[i];
    if (threadIdx.x < 15) sbg[threadIdx.x] = bg[threadIdx.x];
    __syncthreads();

    int v = blockIdx.x * blockDim.x + threadIdx.x;
    if (v >= NN) return;

    float a[15], bb[19];
    float* arow = g_agg + (size_t)v * 16;
#pragma unroll
    for (int i = 0; i < 15; i++) a[i] = fmaxf(arow[i] + sbg[i], 0.0f);
    const float* brow = g_b + (size_t)v * 19;
#pragma unroll
    for (int j = 0; j < 19; j++) bb[j] = brow[j];

    float d2 = g_d2[v];
    float* hrow = g_h + (size_t)v * 16;
#pragma unroll
    for (int o = 0; o < 15; o++) {
        float acc = 0.0f;
        const float* w = sWg + o * 34;
#pragma unroll
        for (int k = 0; k < 15; k++) acc = fmaf(w[k], a[k], acc);
#pragma unroll
        for (int k = 0; k < 19; k++) acc = fmaf(w[15 + k], bb[k], acc);
        hrow[o] = acc;
        arow[o] = acc * d2;   // self-loop contribution
    }
    hrow[15] = 0.0f;
}

// ---- scatter: agg[col] += h[row] * norm  (documented float4 atomicAdd, cc>=9.0) ----
__global__ void k_scatter() {
    int e = blockIdx.x * blockDim.x + threadIdx.x;
    if (e >= NE) return;
    int r = g_rows[e];
    int c = g_cols[e];
    float w = g_norm[e];
    const float4* hp = reinterpret_cast<const float4*>(g_h + (size_t)r * 16);
    float4 h0 = hp[0], h1 = hp[1], h2 = hp[2], h3 = hp[3];
    h0.x *= w; h0.y *= w; h0.z *= w; h0.w *= w;
    h1.x *= w; h1.y *= w; h1.z *= w; h1.w *= w;
    h2.x *= w; h2.y *= w; h2.z *= w; h2.w *= w;
    h3.x *= w; h3.y *= w; h3.z *= w; h3.w *= w;
    float4* ap = reinterpret_cast<float4*>(g_agg + (size_t)c * 16);
    atomicAdd(ap + 0, h0);
    atomicAdd(ap + 1, h1);
    atomicAdd(ap + 2, h2);
    atomicAdd(ap + 3, h3);
}

// ---- final: a = relu(agg+bg); sum_v W3 . [a;b] ----
__global__ void k_final(const float* __restrict__ W3, const float* __restrict__ bg) {
    __shared__ float sW3[34], sbg[15];
    __shared__ float warpsum[32];
    if (threadIdx.x < 34) sW3[threadIdx.x] = W3[threadIdx.x];
    if (threadIdx.x < 15) sbg[threadIdx.x] = bg[threadIdx.x];
    __syncthreads();

    int v = blockIdx.x * blockDim.x + threadIdx.x;
    float acc = 0.0f;
    if (v < NN) {
        const float* arow = g_agg + (size_t)v * 16;
#pragma unroll
        for (int i = 0; i < 15; i++) {
            float a = fmaxf(arow[i] + sbg[i], 0.0f);
            acc = fmaf(sW3[i], a, acc);
        }
        const float* brow = g_b + (size_t)v * 19;
#pragma unroll
        for (int j = 0; j < 19; j++) acc = fmaf(sW3[15 + j], brow[j], acc);
    }
    // block reduce
#pragma unroll
    for (int off = 16; off > 0; off >>= 1)
        acc += __shfl_down_sync(0xFFFFFFFFu, acc, off);
    int lane = threadIdx.x & 31, wid = threadIdx.x >> 5;
    if (lane == 0) warpsum[wid] = acc;
    __syncthreads();
    if (wid == 0) {
        int nwarps = (blockDim.x + 31) >> 5;
        float s = (lane < nwarps) ? warpsum[lane] : 0.0f;
#pragma unroll
        for (int off = 16; off > 0; off >>= 1)
            s += __shfl_down_sync(0xFFFFFFFFu, s, off);
        if (lane == 0) atomicAdd(&g_sum, s);
    }
}

// ---- write output: tanh(sum/N + b3) ----
__global__ void k_out(const float* __restrict__ b3, float* __restrict__ out) {
    out[0] = tanhf(g_sum / (float)NN + b3[0]);
}

extern "C" void kernel_launch(void* const* d_in, const int* in_sizes, int n_in,
                              void* d_out, int out_size) {
    const float* x1    = (const float*)d_in[0];
    const float* x2    = (const float*)d_in[1];
    const void*  edges = d_in[2];                 // int32 or int64, detected on device
    const float* W1    = (const float*)d_in[3];
    const float* b1    = (const float*)d_in[4];
    const float* Wg    = (const float*)d_in[5];
    const float* bg    = (const float*)d_in[6];
    const float* W3    = (const float*)d_in[7];
    const float* b3    = (const float*)d_in[8];
    const float* W4    = (const float*)d_in[9];
    const float* b4    = (const float*)d_in[10];
    float* out = (float*)d_out;

    const int TB = 256;
    const int gN = (NN + TB - 1) / TB;
    const int gE = (NE + TB - 1) / TB;

    k_detect<<<1, 1>>>((const int*)edges);
    k_init<<<gN, TB>>>();
    k_deg<<<gE, TB>>>(edges);
    k_dinv<<<gN, TB>>>();
    k_eprep<<<gE, TB>>>(edges);
    k_ab<<<gN, TB>>>(x1, x2, W4, b4, W1, b1, bg);
    for (int it = 0; it < 5; it++) {
        k_H<<<gN, TB>>>(Wg, bg);
        k_scatter<<<gE, TB>>>();
    }
    k_final<<<gN, TB>>>(W3, bg);
    k_out<<<1, 1>>>(b3, out);
}

// round 7
// speedup vs baseline: 1.3517x; 1.3517x over previous
#include <cuda_runtime.h>
#include <math.h>

#define NN 100000
#define NB 5000
#define NE 3200000
#define SCAN_CHUNK 1024
#define SCAN_NBLK ((NN + SCAN_CHUNK - 1) / SCAN_CHUNK)   // 98

// ---- device scratch ----
__device__ __align__(16) float g_h[NN * 16];    // padded h rows (slot 15 = 0)
__device__ __align__(16) float g_agg[NN * 16];  // padded agg
__device__ float g_b[NN * 19];
__device__ int   g_rows_s[NE];   // CSC: source row per edge, sorted by col
__device__ float g_norm_s[NE];   // fused norm per sorted edge
__device__ int   g_cnt[NN];      // real in-degree (no self loop)
__device__ int   g_off[NN];      // CSC offsets (exclusive scan of cnt)
__device__ int   g_cursor[NN];
__device__ int   g_bsum[SCAN_NBLK];
__device__ float g_dinv[NN];
__device__ float g_d2[NN];       // 1/deg (deg = cnt+1)
__device__ float g_sum;
__device__ int   g_is64;

// ---- detect edge dtype (int64 vs int32): int64 node ids < 1e5 have zero high words ----
__global__ void k_detect(const int* __restrict__ ewords) {
    int nonzero = 0;
    for (int i = 0; i < 64; i++) nonzero |= ewords[2 * i + 1];
    g_is64 = (nonzero == 0) ? 1 : 0;
}

__global__ void k_init() {
    int v = blockIdx.x * blockDim.x + threadIdx.x;
    if (v < NN) { g_cnt[v] = 0; g_cursor[v] = 0; }
    if (v == 0) g_sum = 0.0f;
}

__device__ __forceinline__ int load_edge(const void* edges, int is64, long long idx) {
    if (is64) return (int)((const long long*)edges)[idx];
    return ((const int*)edges)[idx];
}

// ---- in-degree histogram over col ----
__global__ void k_deg(const void* __restrict__ edges) {
    int e = blockIdx.x * blockDim.x + threadIdx.x;
    if (e >= NE) return;
    int c = load_edge(edges, g_is64, (long long)NE + e);
    if ((unsigned)c < (unsigned)NN) atomicAdd(&g_cnt[c], 1);
}

// ---- exclusive prefix sum of cnt -> off  (3-kernel blocked scan) ----
__global__ void k_scan1() {
    __shared__ int s[SCAN_CHUNK];
    int i = blockIdx.x * SCAN_CHUNK + threadIdx.x;
    int v = (i < NN) ? g_cnt[i] : 0;
    s[threadIdx.x] = v;
    __syncthreads();
    for (int d = 1; d < SCAN_CHUNK; d <<= 1) {
        int t = (threadIdx.x >= d) ? s[threadIdx.x - d] : 0;
        __syncthreads();
        s[threadIdx.x] += t;
        __syncthreads();
    }
    if (i < NN) g_off[i] = s[threadIdx.x] - v;                 // exclusive
    if (threadIdx.x == SCAN_CHUNK - 1) g_bsum[blockIdx.x] = s[SCAN_CHUNK - 1];
}

__global__ void k_scan2() {
    __shared__ int s[128];
    int tid = threadIdx.x;
    int v = (tid < SCAN_NBLK) ? g_bsum[tid] : 0;
    s[tid] = v;
    __syncthreads();
    for (int d = 1; d < 128; d <<= 1) {
        int t = (tid >= d) ? s[tid - d] : 0;
        __syncthreads();
        s[tid] += t;
        __syncthreads();
    }
    if (tid < SCAN_NBLK) g_bsum[tid] = s[tid] - v;             // exclusive
}

__global__ void k_scan3() {
    int i = blockIdx.x * blockDim.x + threadIdx.x;
    if (i < NN) g_off[i] += g_bsum[i / SCAN_CHUNK];
}

// ---- dinv / d2 from deg = cnt + 1 (self loop) ----
__global__ void k_dinv() {
    int v = blockIdx.x * blockDim.x + threadIdx.x;
    if (v >= NN) return;
    float d = (float)(g_cnt[v] + 1);
    g_dinv[v] = 1.0f / sqrtf(d);
    g_d2[v]   = 1.0f / d;
}

// ---- place edges into CSC, fused norm ----
__global__ void k_place(const void* __restrict__ edges) {
    int e = blockIdx.x * blockDim.x + threadIdx.x;
    if (e >= NE) return;
    int is64 = g_is64;
    int r = load_edge(edges, is64, e);
    int c = load_edge(edges, is64, (long long)NE + e);
    if ((unsigned)r >= (unsigned)NN) r = 0;
    if ((unsigned)c >= (unsigned)NN) c = 0;
    int p = atomicAdd(&g_cursor[c], 1);
    int idx = g_off[c] + p;
    g_rows_s[idx] = r;
    g_norm_s[idx] = g_dinv[r] * g_dinv[c];
}

// ---- b = [x1|x2t] W4^T + b4 ; agg0 = x1 W1^T + b1 - bg (pre-relu a0) ----
__global__ void k_ab(const float* __restrict__ x1, const float* __restrict__ x2,
                     const float* __restrict__ W4, const float* __restrict__ b4,
                     const float* __restrict__ W1, const float* __restrict__ b1,
                     const float* __restrict__ bg) {
    __shared__ float sW4[19 * 19], sb4[19], sW1[15 * 15], sb1[15], sbg[15];
    for (int i = threadIdx.x; i < 19 * 19; i += blockDim.x) sW4[i] = W4[i];
    for (int i = threadIdx.x; i < 15 * 15; i += blockDim.x) sW1[i] = W1[i];
    if (threadIdx.x < 19) sb4[threadIdx.x] = b4[threadIdx.x];
    if (threadIdx.x < 15) { sb1[threadIdx.x] = b1[threadIdx.x]; sbg[threadIdx.x] = bg[threadIdx.x]; }
    __syncthreads();

    int v = blockIdx.x * blockDim.x + threadIdx.x;
    if (v >= NN) return;

    float in[19];
    const float* x1r = x1 + (size_t)v * 15;
#pragma unroll
    for (int k = 0; k < 15; k++) in[k] = x1r[k];
    const float* x2r = x2 + (size_t)(v % NB) * 4;
#pragma unroll
    for (int k = 0; k < 4; k++) in[15 + k] = x2r[k];

    float* brow = g_b + (size_t)v * 19;
#pragma unroll
    for (int j = 0; j < 19; j++) {
        float acc = sb4[j];
#pragma unroll
        for (int k = 0; k < 19; k++) acc = fmaf(sW4[j * 19 + k], in[k], acc);
        brow[j] = acc;
    }

    float* arow = g_agg + (size_t)v * 16;
#pragma unroll
    for (int i = 0; i < 15; i++) {
        float acc = sb1[i] - sbg[i];
#pragma unroll
        for (int k = 0; k < 15; k++) acc = fmaf(sW1[i * 15 + k], in[k], acc);
        arow[i] = acc;
    }
    arow[15] = 0.0f;
}

// ---- kernel H: a = relu(agg+bg); h = Wg [a;b] ----
__global__ void k_H(const float* __restrict__ Wg, const float* __restrict__ bg) {
    __shared__ float sWg[15 * 34], sbg[15];
    for (int i = threadIdx.x; i < 15 * 34; i += blockDim.x) sWg[i] = Wg[i];
    if (threadIdx.x < 15) sbg[threadIdx.x] = bg[threadIdx.x];
    __syncthreads();

    int v = blockIdx.x * blockDim.x + threadIdx.x;
    if (v >= NN) return;

    float a[15], bb[19];
    const float* arow = g_agg + (size_t)v * 16;
#pragma unroll
    for (int i = 0; i < 15; i++) a[i] = fmaxf(arow[i] + sbg[i], 0.0f);
    const float* brow = g_b + (size_t)v * 19;
#pragma unroll
    for (int j = 0; j < 19; j++) bb[j] = brow[j];

    float* hrow = g_h + (size_t)v * 16;
#pragma unroll
    for (int o = 0; o < 15; o++) {
        float acc = 0.0f;
        const float* w = sWg + o * 34;
#pragma unroll
        for (int k = 0; k < 15; k++) acc = fmaf(w[k], a[k], acc);
#pragma unroll
        for (int k = 0; k < 19; k++) acc = fmaf(w[15 + k], bb[k], acc);
        hrow[o] = acc;
    }
    hrow[15] = 0.0f;
}

// ---- gather: agg[v] = h[v]*d2 + sum_j h[rows_s[j]] * norm_s[j]  (16 threads/node) ----
__global__ void k_gather() {
    int v = blockIdx.x * (256 / 16) + (threadIdx.x >> 4);   // NN = 6250*16 exactly
    int t = threadIdx.x & 15;
    if (v >= NN) return;

    int off = g_off[v];
    int cnt = g_cnt[v];
    float acc = g_h[(size_t)v * 16 + t] * g_d2[v];   // self loop

    int base = 0;
    for (; base + 16 <= cnt; base += 16) {
        int   rj = g_rows_s[off + base + t];   // coalesced batch of 16
        float wj = g_norm_s[off + base + t];
#pragma unroll
        for (int j = 0; j < 16; j++) {
            int   r = __shfl_sync(0xFFFFFFFFu, rj, j, 16);
            float w = __shfl_sync(0xFFFFFFFFu, wj, j, 16);
            acc = fmaf(g_h[(size_t)r * 16 + t], w, acc);  // coalesced 64B row
        }
    }
    for (; base < cnt; base++) {
        int   r = g_rows_s[off + base];        // broadcast
        float w = g_norm_s[off + base];
        acc = fmaf(g_h[(size_t)r * 16 + t], w, acc);
    }
    g_agg[(size_t)v * 16 + t] = acc;
}

// ---- final: a = relu(agg+bg); sum_v W3 . [a;b] ----
__global__ void k_final(const float* __restrict__ W3, const float* __restrict__ bg) {
    __shared__ float sW3[34], sbg[15];
    __shared__ float warpsum[32];
    if (threadIdx.x < 34) sW3[threadIdx.x] = W3[threadIdx.x];
    if (threadIdx.x < 15) sbg[threadIdx.x] = bg[threadIdx.x];
    __syncthreads();

    int v = blockIdx.x * blockDim.x + threadIdx.x;
    float acc = 0.0f;
    if (v < NN) {
        const float* arow = g_agg + (size_t)v * 16;
#pragma unroll
        for (int i = 0; i < 15; i++) {
            float a = fmaxf(arow[i] + sbg[i], 0.0f);
            acc = fmaf(sW3[i], a, acc);
        }
        const float* brow = g_b + (size_t)v * 19;
#pragma unroll
        for (int j = 0; j < 19; j++) acc = fmaf(sW3[15 + j], brow[j], acc);
    }
#pragma unroll
    for (int off = 16; off > 0; off >>= 1)
        acc += __shfl_down_sync(0xFFFFFFFFu, acc, off);
    int lane = threadIdx.x & 31, wid = threadIdx.x >> 5;
    if (lane == 0) warpsum[wid] = acc;
    __syncthreads();
    if (wid == 0) {
        int nwarps = (blockDim.x + 31) >> 5;
        float s = (lane < nwarps) ? warpsum[lane] : 0.0f;
#pragma unroll
        for (int off = 16; off > 0; off >>= 1)
            s += __shfl_down_sync(0xFFFFFFFFu, s, off);
        if (lane == 0) atomicAdd(&g_sum, s);
    }
}

__global__ void k_out(const float* __restrict__ b3, float* __restrict__ out) {
    out[0] = tanhf(g_sum / (float)NN + b3[0]);
}

extern "C" void kernel_launch(void* const* d_in, const int* in_sizes, int n_in,
                              void* d_out, int out_size) {
    const float* x1    = (const float*)d_in[0];
    const float* x2    = (const float*)d_in[1];
    const void*  edges = d_in[2];
    const float* W1    = (const float*)d_in[3];
    const float* b1    = (const float*)d_in[4];
    const float* Wg    = (const float*)d_in[5];
    const float* bg    = (const float*)d_in[6];
    const float* W3    = (const float*)d_in[7];
    const float* b3    = (const float*)d_in[8];
    const float* W4    = (const float*)d_in[9];
    const float* b4    = (const float*)d_in[10];
    float* out = (float*)d_out;

    const int TB = 256;
    const int gN = (NN + TB - 1) / TB;
    const int gE = (NE + TB - 1) / TB;

    k_detect<<<1, 1>>>((const int*)edges);
    k_init<<<gN, TB>>>();
    k_deg<<<gE, TB>>>(edges);
    k_scan1<<<SCAN_NBLK, SCAN_CHUNK>>>();
    k_scan2<<<1, 128>>>();
    k_scan3<<<gN, TB>>>();
    k_dinv<<<gN, TB>>>();
    k_place<<<gE, TB>>>(edges);
    k_ab<<<gN, TB>>>(x1, x2, W4, b4, W1, b1, bg);
    for (int it = 0; it < 5; it++) {
        k_H<<<gN, TB>>>(Wg, bg);
        k_gather<<<NN / 16, TB>>>();
    }
    k_final<<<gN, TB>>>(W3, bg);
    k_out<<<1, 1>>>(b3, out);
}

// round 8
// speedup vs baseline: 1.3864x; 1.0257x over previous
#include <cuda_runtime.h>
#include <math.h>

#define NN 100000
#define NB 5000
#define NE 3200000
#define SCAN_CHUNK 1024
#define SCAN_NBLK ((NN + SCAN_CHUNK - 1) / SCAN_CHUNK)   // 98

// ---- device scratch ----
__device__ __align__(16) float g_h[NN * 16];    // padded h rows (slot 15 = 0)
__device__ __align__(16) float g_agg[NN * 16];  // padded agg
__device__ float g_b[NN * 19];
__device__ __align__(8) int2 g_adj[NE];         // CSC: {src row, norm bits} per edge, sorted by col
__device__ int   g_cnt[NN];      // in-degree (no self loop)
__device__ int   g_off[NN];      // CSC offsets
__device__ int   g_cursor[NN];
__device__ int   g_bsum[SCAN_NBLK];
__device__ float g_dinv[NN];
__device__ float g_d2[NN];       // 1/deg (deg = cnt+1)
__device__ float g_sum;
__device__ int   g_is64;

// ---- detect edge dtype + init counters ----
// int64 node ids < 1e5 have zero high 32-bit words; int32 data ~never does.
__global__ void k_init(const int* __restrict__ ewords) {
    int v = blockIdx.x * blockDim.x + threadIdx.x;
    if (v < NN) { g_cnt[v] = 0; g_cursor[v] = 0; }
    if (v == 0) {
        int nonzero = 0;
        for (int i = 0; i < 64; i++) nonzero |= ewords[2 * i + 1];
        g_is64 = (nonzero == 0) ? 1 : 0;
        g_sum = 0.0f;
    }
}

__device__ __forceinline__ int load_edge(const void* edges, int is64, long long idx) {
    if (is64) return (int)((const long long*)edges)[idx];
    return ((const int*)edges)[idx];
}

// ---- in-degree histogram over col ----
__global__ void k_deg(const void* __restrict__ edges) {
    int e = blockIdx.x * blockDim.x + threadIdx.x;
    if (e >= NE) return;
    int c = load_edge(edges, g_is64, (long long)NE + e);
    if ((unsigned)c < (unsigned)NN) atomicAdd(&g_cnt[c], 1);
}

// ---- blocked exclusive scan of cnt -> off ----
__global__ void k_scan1() {
    __shared__ int s[SCAN_CHUNK];
    int i = blockIdx.x * SCAN_CHUNK + threadIdx.x;
    int v = (i < NN) ? g_cnt[i] : 0;
    s[threadIdx.x] = v;
    __syncthreads();
    for (int d = 1; d < SCAN_CHUNK; d <<= 1) {
        int t = (threadIdx.x >= d) ? s[threadIdx.x - d] : 0;
        __syncthreads();
        s[threadIdx.x] += t;
        __syncthreads();
    }
    if (i < NN) g_off[i] = s[threadIdx.x] - v;
    if (threadIdx.x == SCAN_CHUNK - 1) g_bsum[blockIdx.x] = s[SCAN_CHUNK - 1];
}

__global__ void k_scan2() {
    __shared__ int s[128];
    int tid = threadIdx.x;
    int v = (tid < SCAN_NBLK) ? g_bsum[tid] : 0;
    s[tid] = v;
    __syncthreads();
    for (int d = 1; d < 128; d <<= 1) {
        int t = (tid >= d) ? s[tid - d] : 0;
        __syncthreads();
        s[tid] += t;
        __syncthreads();
    }
    if (tid < SCAN_NBLK) g_bsum[tid] = s[tid] - v;
}

// ---- scan fixup + dinv/d2 (fused) ----
__global__ void k_scan3() {
    int i = blockIdx.x * blockDim.x + threadIdx.x;
    if (i >= NN) return;
    g_off[i] += g_bsum[i / SCAN_CHUNK];
    float d = (float)(g_cnt[i] + 1);
    g_dinv[i] = 1.0f / sqrtf(d);
    g_d2[i]   = 1.0f / d;
}

// ---- place edges into CSC: single packed STG.64 per edge ----
__global__ void k_place(const void* __restrict__ edges) {
    int e = blockIdx.x * blockDim.x + threadIdx.x;
    if (e >= NE) return;
    int is64 = g_is64;
    int r = load_edge(edges, is64, e);
    int c = load_edge(edges, is64, (long long)NE + e);
    if ((unsigned)r >= (unsigned)NN) r = 0;
    if ((unsigned)c >= (unsigned)NN) c = 0;
    int p = atomicAdd(&g_cursor[c], 1);
    int2 rec;
    rec.x = r;
    rec.y = __float_as_int(g_dinv[r] * g_dinv[c]);
    g_adj[g_off[c] + p] = rec;
}

// ---- b = [x1|x2t] W4^T + b4 ; agg0 = x1 W1^T + b1 - bg ----
__global__ void k_ab(const float* __restrict__ x1, const float* __restrict__ x2,
                     const float* __restrict__ W4, const float* __restrict__ b4,
                     const float* __restrict__ W1, const float* __restrict__ b1,
                     const float* __restrict__ bg) {
    __shared__ float sW4[19 * 19], sb4[19], sW1[15 * 15], sb1[15], sbg[15];
    for (int i = threadIdx.x; i < 19 * 19; i += blockDim.x) sW4[i] = W4[i];
    for (int i = threadIdx.x; i < 15 * 15; i += blockDim.x) sW1[i] = W1[i];
    if (threadIdx.x < 19) sb4[threadIdx.x] = b4[threadIdx.x];
    if (threadIdx.x < 15) { sb1[threadIdx.x] = b1[threadIdx.x]; sbg[threadIdx.x] = bg[threadIdx.x]; }
    __syncthreads();

    int v = blockIdx.x * blockDim.x + threadIdx.x;
    if (v >= NN) return;

    float in[19];
    const float* x1r = x1 + (size_t)v * 15;
#pragma unroll
    for (int k = 0; k < 15; k++) in[k] = x1r[k];
    const float* x2r = x2 + (size_t)(v % NB) * 4;
#pragma unroll
    for (int k = 0; k < 4; k++) in[15 + k] = x2r[k];

    float* brow = g_b + (size_t)v * 19;
#pragma unroll
    for (int j = 0; j < 19; j++) {
        float acc = sb4[j];
#pragma unroll
        for (int k = 0; k < 19; k++) acc = fmaf(sW4[j * 19 + k], in[k], acc);
        brow[j] = acc;
    }

    float* arow = g_agg + (size_t)v * 16;
#pragma unroll
    for (int i = 0; i < 15; i++) {
        float acc = sb1[i] - sbg[i];
#pragma unroll
        for (int k = 0; k < 15; k++) acc = fmaf(sW1[i * 15 + k], in[k], acc);
        arow[i] = acc;
    }
    arow[15] = 0.0f;
}

// ---- kernel H: a = relu(agg+bg); h = Wg [a;b] ----
__global__ void k_H(const float* __restrict__ Wg, const float* __restrict__ bg) {
    __shared__ float sWg[15 * 34], sbg[15];
    for (int i = threadIdx.x; i < 15 * 34; i += blockDim.x) sWg[i] = Wg[i];
    if (threadIdx.x < 15) sbg[threadIdx.x] = bg[threadIdx.x];
    __syncthreads();

    int v = blockIdx.x * blockDim.x + threadIdx.x;
    if (v >= NN) return;

    float a[15], bb[19];
    const float* arow = g_agg + (size_t)v * 16;
#pragma unroll
    for (int i = 0; i < 15; i++) a[i] = fmaxf(arow[i] + sbg[i], 0.0f);
    const float* brow = g_b + (size_t)v * 19;
#pragma unroll
    for (int j = 0; j < 19; j++) bb[j] = brow[j];

    float* hrow = g_h + (size_t)v * 16;
#pragma unroll
    for (int o = 0; o < 15; o++) {
        float acc = 0.0f;
        const float* w = sWg + o * 34;
#pragma unroll
        for (int k = 0; k < 15; k++) acc = fmaf(w[k], a[k], acc);
#pragma unroll
        for (int k = 0; k < 19; k++) acc = fmaf(w[15 + k], bb[k], acc);
        hrow[o] = acc;
    }
    hrow[15] = 0.0f;
}

// ---- gather (software-pipelined): agg[v] = h[v]*d2 + sum_j h[adj.r]*adj.w ----
__global__ void k_gather() {
    int v = blockIdx.x * (256 / 16) + (threadIdx.x >> 4);
    int t = threadIdx.x & 15;
    if (v >= NN) return;

    int off = g_off[v];
    int cnt = g_cnt[v];
    float acc = g_h[(size_t)v * 16 + t] * g_d2[v];   // self loop

    int nb = cnt >> 4;                // full 16-edge batches
    int2 cur = make_int2(0, 0);
    if (nb > 0) cur = g_adj[off + t]; // coalesced 128B batch load

    for (int bidx = 0; bidx < nb; bidx++) {
        int2 nxt = make_int2(0, 0);
        if (bidx + 1 < nb) nxt = g_adj[off + (bidx + 1) * 16 + t];  // prefetch
#pragma unroll
        for (int j = 0; j < 16; j++) {
            int   r = __shfl_sync(0xFFFFFFFFu, cur.x, j, 16);
            float w = __int_as_float(__shfl_sync(0xFFFFFFFFu, cur.y, j, 16));
            acc = fmaf(g_h[(size_t)r * 16 + t], w, acc);   // coalesced 64B row
        }
        cur = nxt;
    }
    for (int base = nb << 4; base < cnt; base++) {
        int2 rw = g_adj[off + base];                        // broadcast load
        acc = fmaf(g_h[(size_t)rw.x * 16 + t], __int_as_float(rw.y), acc);
    }
    g_agg[(size_t)v * 16 + t] = acc;
}

// ---- final: a = relu(agg+bg); sum_v W3 . [a;b] ----
__global__ void k_final(const float* __restrict__ W3, const float* __restrict__ bg) {
    __shared__ float sW3[34], sbg[15];
    __shared__ float warpsum[32];
    if (threadIdx.x < 34) sW3[threadIdx.x] = W3[threadIdx.x];
    if (threadIdx.x < 15) sbg[threadIdx.x] = bg[threadIdx.x];
    __syncthreads();

    int v = blockIdx.x * blockDim.x + threadIdx.x;
    float acc = 0.0f;
    if (v < NN) {
        const float* arow = g_agg + (size_t)v * 16;
#pragma unroll
        for (int i = 0; i < 15; i++) {
            float a = fmaxf(arow[i] + sbg[i], 0.0f);
            acc = fmaf(sW3[i], a, acc);
        }
        const float* brow = g_b + (size_t)v * 19;
#pragma unroll
        for (int j = 0; j < 19; j++) acc = fmaf(sW3[15 + j], brow[j], acc);
    }
#pragma unroll
    for (int off = 16; off > 0; off >>= 1)
        acc += __shfl_down_sync(0xFFFFFFFFu, acc, off);
    int lane = threadIdx.x & 31, wid = threadIdx.x >> 5;
    if (lane == 0) warpsum[wid] = acc;
    __syncthreads();
    if (wid == 0) {
        int nwarps = (blockDim.x + 31) >> 5;
        float s = (lane < nwarps) ? warpsum[lane] : 0.0f;
#pragma unroll
        for (int off = 16; off > 0; off >>= 1)
            s += __shfl_down_sync(0xFFFFFFFFu, s, off);
        if (lane == 0) atomicAdd(&g_sum, s);
    }
}

__global__ void k_out(const float* __restrict__ b3, float* __restrict__ out) {
    out[0] = tanhf(g_sum / (float)NN + b3[0]);
}

extern "C" void kernel_launch(void* const* d_in, const int* in_sizes, int n_in,
                              void* d_out, int out_size) {
    const float* x1    = (const float*)d_in[0];
    const float* x2    = (const float*)d_in[1];
    const void*  edges = d_in[2];
    const float* W1    = (const float*)d_in[3];
    const float* b1    = (const float*)d_in[4];
    const float* Wg    = (const float*)d_in[5];
    const float* bg    = (const float*)d_in[6];
    const float* W3    = (const float*)d_in[7];
    const float* b3    = (const float*)d_in[8];
    const float* W4    = (const float*)d_in[9];
    const float* b4    = (const float*)d_in[10];
    float* out = (float*)d_out;

    const int TB = 256;
    const int gN = (NN + TB - 1) / TB;
    const int gE = (NE + TB - 1) / TB;

    k_init<<<gN, TB>>>((const int*)edges);
    k_deg<<<gE, TB>>>(edges);
    k_scan1<<<SCAN_NBLK, SCAN_CHUNK>>>();
    k_scan2<<<1, 128>>>();
    k_scan3<<<gN, TB>>>();
    k_place<<<gE, TB>>>(edges);
    k_ab<<<gN, TB>>>(x1, x2, W4, b4, W1, b1, bg);
    for (int it = 0; it < 5; it++) {
        k_H<<<gN, TB>>>(Wg, bg);
        k_gather<<<NN / 16, TB>>>();
    }
    k_final<<<gN, TB>>>(W3, bg);
    k_out<<<1, 1>>>(b3, out);
}

// round 9
// speedup vs baseline: 1.4601x; 1.0532x over previous
#include <cuda_runtime.h>
#include <math.h>

#define NN 100000
#define NB 5000
#define NE 3200000
#define SCAN_CHUNK 1024
#define SCAN_NBLK ((NN + SCAN_CHUNK - 1) / SCAN_CHUNK)   // 98

// ---- device scratch ----
__device__ __align__(16) float g_h[NN * 16];    // padded h rows (slot 15 = 0)
__device__ __align__(16) float g_agg[NN * 16];  // padded agg
__device__ float g_b[NN * 19];
__device__ __align__(8) int2 g_adj[NE];         // CSC: {src row, norm bits}, sorted by col
__device__ int   g_cnt[NN];      // in-degree (no self loop)
__device__ int   g_off[NN];      // CSC offsets
__device__ int   g_cursor[NN];
__device__ int   g_bsum[SCAN_NBLK];
__device__ float g_dinv[NN];
__device__ float g_d2[NN];       // 1/deg (deg = cnt+1)
__device__ float g_sum;
__device__ int   g_is64;

// ---- detect edge dtype + init counters ----
__global__ void k_init(const int* __restrict__ ewords) {
    int v = blockIdx.x * blockDim.x + threadIdx.x;
    if (v < NN) { g_cnt[v] = 0; g_cursor[v] = 0; }
    if (v == 0) {
        int nonzero = 0;
        for (int i = 0; i < 64; i++) nonzero |= ewords[2 * i + 1];
        g_is64 = (nonzero == 0) ? 1 : 0;
        g_sum = 0.0f;
    }
}

__device__ __forceinline__ int load_edge(const void* edges, int is64, long long idx) {
    if (is64) return (int)((const long long*)edges)[idx];
    return ((const int*)edges)[idx];
}

// ---- in-degree histogram over col ----
__global__ void k_deg(const void* __restrict__ edges) {
    int e = blockIdx.x * blockDim.x + threadIdx.x;
    if (e >= NE) return;
    int c = load_edge(edges, g_is64, (long long)NE + e);
    if ((unsigned)c < (unsigned)NN) atomicAdd(&g_cnt[c], 1);
}

// ---- blocked exclusive scan of cnt -> off ----
__global__ void k_scan1() {
    __shared__ int s[SCAN_CHUNK];
    int i = blockIdx.x * SCAN_CHUNK + threadIdx.x;
    int v = (i < NN) ? g_cnt[i] : 0;
    s[threadIdx.x] = v;
    __syncthreads();
    for (int d = 1; d < SCAN_CHUNK; d <<= 1) {
        int t = (threadIdx.x >= d) ? s[threadIdx.x - d] : 0;
        __syncthreads();
        s[threadIdx.x] += t;
        __syncthreads();
    }
    if (i < NN) g_off[i] = s[threadIdx.x] - v;
    if (threadIdx.x == SCAN_CHUNK - 1) g_bsum[blockIdx.x] = s[SCAN_CHUNK - 1];
}

__global__ void k_scan2() {
    __shared__ int s[128];
    int tid = threadIdx.x;
    int v = (tid < SCAN_NBLK) ? g_bsum[tid] : 0;
    s[tid] = v;
    __syncthreads();
    for (int d = 1; d < 128; d <<= 1) {
        int t = (tid >= d) ? s[tid - d] : 0;
        __syncthreads();
        s[tid] += t;
        __syncthreads();
    }
    if (tid < SCAN_NBLK) g_bsum[tid] = s[tid] - v;
}

// ---- scan fixup + dinv/d2 (fused) ----
__global__ void k_scan3() {
    int i = blockIdx.x * blockDim.x + threadIdx.x;
    if (i >= NN) return;
    g_off[i] += g_bsum[i / SCAN_CHUNK];
    float d = (float)(g_cnt[i] + 1);
    g_dinv[i] = 1.0f / sqrtf(d);
    g_d2[i]   = 1.0f / d;
}

// ---- place edges into CSC: single packed STG.64 per edge ----
__global__ void k_place(const void* __restrict__ edges) {
    int e = blockIdx.x * blockDim.x + threadIdx.x;
    if (e >= NE) return;
    int is64 = g_is64;
    int r = load_edge(edges, is64, e);
    int c = load_edge(edges, is64, (long long)NE + e);
    if ((unsigned)r >= (unsigned)NN) r = 0;
    if ((unsigned)c >= (unsigned)NN) c = 0;
    int p = atomicAdd(&g_cursor[c], 1);
    int2 rec;
    rec.x = r;
    rec.y = __float_as_int(g_dinv[r] * g_dinv[c]);
    g_adj[g_off[c] + p] = rec;
}

// ---- b = [x1|x2t] W4^T + b4 ; agg0 = x1 W1^T + b1 - bg ----
__global__ void k_ab(const float* __restrict__ x1, const float* __restrict__ x2,
                     const float* __restrict__ W4, const float* __restrict__ b4,
                     const float* __restrict__ W1, const float* __restrict__ b1,
                     const float* __restrict__ bg) {
    __shared__ float sW4[19 * 19], sb4[19], sW1[15 * 15], sb1[15], sbg[15];
    for (int i = threadIdx.x; i < 19 * 19; i += blockDim.x) sW4[i] = W4[i];
    for (int i = threadIdx.x; i < 15 * 15; i += blockDim.x) sW1[i] = W1[i];
    if (threadIdx.x < 19) sb4[threadIdx.x] = b4[threadIdx.x];
    if (threadIdx.x < 15) { sb1[threadIdx.x] = b1[threadIdx.x]; sbg[threadIdx.x] = bg[threadIdx.x]; }
    __syncthreads();

    int v = blockIdx.x * blockDim.x + threadIdx.x;
    if (v >= NN) return;

    float in[19];
    const float* x1r = x1 + (size_t)v * 15;
#pragma unroll
    for (int k = 0; k < 15; k++) in[k] = x1r[k];
    const float* x2r = x2 + (size_t)(v % NB) * 4;
#pragma unroll
    for (int k = 0; k < 4; k++) in[15 + k] = x2r[k];

    float* brow = g_b + (size_t)v * 19;
#pragma unroll
    for (int j = 0; j < 19; j++) {
        float acc = sb4[j];
#pragma unroll
        for (int k = 0; k < 19; k++) acc = fmaf(sW4[j * 19 + k], in[k], acc);
        brow[j] = acc;
    }

    float* arow = g_agg + (size_t)v * 16;
#pragma unroll
    for (int i = 0; i < 15; i++) {
        float acc = sb1[i] - sbg[i];
#pragma unroll
        for (int k = 0; k < 15; k++) acc = fmaf(sW1[i * 15 + k], in[k], acc);
        arow[i] = acc;
    }
    arow[15] = 0.0f;
}

// ---- kernel H: a = relu(agg+bg); h = Wg [a;b] ----
__global__ void k_H(const float* __restrict__ Wg, const float* __restrict__ bg) {
    __shared__ float sWg[15 * 34], sbg[15];
    for (int i = threadIdx.x; i < 15 * 34; i += blockDim.x) sWg[i] = Wg[i];
    if (threadIdx.x < 15) sbg[threadIdx.x] = bg[threadIdx.x];
    __syncthreads();

    int v = blockIdx.x * blockDim.x + threadIdx.x;
    if (v >= NN) return;

    float a[15], bb[19];
    const float* arow = g_agg + (size_t)v * 16;
#pragma unroll
    for (int i = 0; i < 15; i++) a[i] = fmaxf(arow[i] + sbg[i], 0.0f);
    const float* brow = g_b + (size_t)v * 19;
#pragma unroll
    for (int j = 0; j < 19; j++) bb[j] = brow[j];

    float* hrow = g_h + (size_t)v * 16;
#pragma unroll
    for (int o = 0; o < 15; o++) {
        float acc = 0.0f;
        const float* w = sWg + o * 34;
#pragma unroll
        for (int k = 0; k < 15; k++) acc = fmaf(w[k], a[k], acc);
#pragma unroll
        for (int k = 0; k < 19; k++) acc = fmaf(w[15 + k], bb[k], acc);
        hrow[o] = acc;
    }
    hrow[15] = 0.0f;
}

// ---- gather: 16 threads/node, broadcast adj loads, 4 indep FMA chains, 8x unroll ----
__global__ void k_gather() {
    int v = blockIdx.x * 16 + (threadIdx.x >> 4);   // 256 threads = 16 nodes/block
    int t = threadIdx.x & 15;

    int off = g_off[v];
    int cnt = g_cnt[v];
    const int2* __restrict__ ap = g_adj + off;

    float a0 = g_h[(size_t)v * 16 + t] * g_d2[v];   // self loop
    float a1 = 0.0f, a2 = 0.0f, a3 = 0.0f;

    int j = 0;
    for (; j + 8 <= cnt; j += 8) {
        int2 e0 = __ldg(ap + j + 0);
        int2 e1 = __ldg(ap + j + 1);
        int2 e2 = __ldg(ap + j + 2);
        int2 e3 = __ldg(ap + j + 3);
        int2 e4 = __ldg(ap + j + 4);
        int2 e5 = __ldg(ap + j + 5);
        int2 e6 = __ldg(ap + j + 6);
        int2 e7 = __ldg(ap + j + 7);
        float h0 = g_h[(size_t)e0.x * 16 + t];
        float h1 = g_h[(size_t)e1.x * 16 + t];
        float h2 = g_h[(size_t)e2.x * 16 + t];
        float h3 = g_h[(size_t)e3.x * 16 + t];
        float h4 = g_h[(size_t)e4.x * 16 + t];
        float h5 = g_h[(size_t)e5.x * 16 + t];
        float h6 = g_h[(size_t)e6.x * 16 + t];
        float h7 = g_h[(size_t)e7.x * 16 + t];
        a0 = fmaf(h0, __int_as_float(e0.y), a0);
        a1 = fmaf(h1, __int_as_float(e1.y), a1);
        a2 = fmaf(h2, __int_as_float(e2.y), a2);
        a3 = fmaf(h3, __int_as_float(e3.y), a3);
        a0 = fmaf(h4, __int_as_float(e4.y), a0);
        a1 = fmaf(h5, __int_as_float(e5.y), a1);
        a2 = fmaf(h6, __int_as_float(e6.y), a2);
        a3 = fmaf(h7, __int_as_float(e7.y), a3);
    }
    for (; j < cnt; j++) {
        int2 e = __ldg(ap + j);
        a0 = fmaf(g_h[(size_t)e.x * 16 + t], __int_as_float(e.y), a0);
    }
    g_agg[(size_t)v * 16 + t] = (a0 + a1) + (a2 + a3);
}

// ---- final: a = relu(agg+bg); sum_v W3 . [a;b] ----
__global__ void k_final(const float* __restrict__ W3, const float* __restrict__ bg) {
    __shared__ float sW3[34], sbg[15];
    __shared__ float warpsum[32];
    if (threadIdx.x < 34) sW3[threadIdx.x] = W3[threadIdx.x];
    if (threadIdx.x < 15) sbg[threadIdx.x] = bg[threadIdx.x];
    __syncthreads();

    int v = blockIdx.x * blockDim.x + threadIdx.x;
    float acc = 0.0f;
    if (v < NN) {
        const float* arow = g_agg + (size_t)v * 16;
#pragma unroll
        for (int i = 0; i < 15; i++) {
            float a = fmaxf(arow[i] + sbg[i], 0.0f);
            acc = fmaf(sW3[i], a, acc);
        }
        const float* brow = g_b + (size_t)v * 19;
#pragma unroll
        for (int j = 0; j < 19; j++) acc = fmaf(sW3[15 + j], brow[j], acc);
    }
#pragma unroll
    for (int off = 16; off > 0; off >>= 1)
        acc += __shfl_down_sync(0xFFFFFFFFu, acc, off);
    int lane = threadIdx.x & 31, wid = threadIdx.x >> 5;
    if (lane == 0) warpsum[wid] = acc;
    __syncthreads();
    if (wid == 0) {
        int nwarps = (blockDim.x + 31) >> 5;
        float s = (lane < nwarps) ? warpsum[lane] : 0.0f;
#pragma unroll
        for (int off = 16; off > 0; off >>= 1)
            s += __shfl_down_sync(0xFFFFFFFFu, s, off);
        if (lane == 0) atomicAdd(&g_sum, s);
    }
}

__global__ void k_out(const float* __restrict__ b3, float* __restrict__ out) {
    out[0] = tanhf(g_sum / (float)NN + b3[0]);
}

extern "C" void kernel_launch(void* const* d_in, const int* in_sizes, int n_in,
                              void* d_out, int out_size) {
    const float* x1    = (const float*)d_in[0];
    const float* x2    = (const float*)d_in[1];
    const void*  edges = d_in[2];
    const float* W1    = (const float*)d_in[3];
    const float* b1    = (const float*)d_in[4];
    const float* Wg    = (const float*)d_in[5];
    const float* bg    = (const float*)d_in[6];
    const float* W3    = (const float*)d_in[7];
    const float* b3    = (const float*)d_in[8];
    const float* W4    = (const float*)d_in[9];
    const float* b4    = (const float*)d_in[10];
    float* out = (float*)d_out;

    const int TB = 256;
    const int gN = (NN + TB - 1) / TB;
    const int gE = (NE + TB - 1) / TB;

    k_init<<<gN, TB>>>((const int*)edges);
    k_deg<<<gE, TB>>>(edges);
    k_scan1<<<SCAN_NBLK, SCAN_CHUNK>>>();
    k_scan2<<<1, 128>>>();
    k_scan3<<<gN, TB>>>();
    k_place<<<gE, TB>>>(edges);
    k_ab<<<gN, TB>>>(x1, x2, W4, b4, W1, b1, bg);
    for (int it = 0; it < 5; it++) {
        k_H<<<gN, TB>>>(Wg, bg);
        k_gather<<<NN / 16, TB>>>();
    }
    k_final<<<gN, TB>>>(W3, bg);
    k_out<<<1, 1>>>(b3, out);
}

// round 10
// speedup vs baseline: 1.9305x; 1.3221x over previous
#include <cuda_runtime.h>
#include <math.h>

#define NN 100000
#define NB 5000
#define NE 3200000
#define SCAN_CHUNK 1024
#define SCAN_NBLK ((NN + SCAN_CHUNK - 1) / SCAN_CHUNK)   // 98

// ---- device scratch ----
__device__ __align__(16) float g_h[NN * 16];    // padded h rows (slot 15 = 0)
__device__ __align__(16) float g_agg[NN * 16];  // padded agg
__device__ float g_b[NN * 19];
__device__ __align__(8) int2 g_adj[NE];         // CSC: {src row, norm bits}, sorted by col
__device__ int   g_cnt[NN];      // in-degree (no self loop)
__device__ int   g_off[NN];      // CSC offsets
__device__ int   g_cursor[NN];
__device__ int   g_bsum[SCAN_NBLK];
__device__ float g_dinv[NN];
__device__ float g_d2[NN];       // 1/deg (deg = cnt+1)
__device__ float g_sum;
__device__ int   g_is64;

// ---- detect edge dtype + init counters ----
__global__ void k_init(const int* __restrict__ ewords) {
    int v = blockIdx.x * blockDim.x + threadIdx.x;
    if (v < NN) { g_cnt[v] = 0; g_cursor[v] = 0; }
    if (v == 0) {
        int nonzero = 0;
        for (int i = 0; i < 64; i++) nonzero |= ewords[2 * i + 1];
        g_is64 = (nonzero == 0) ? 1 : 0;
        g_sum = 0.0f;
    }
}

__device__ __forceinline__ int load_edge(const void* edges, int is64, long long idx) {
    if (is64) return (int)((const long long*)edges)[idx];
    return ((const int*)edges)[idx];
}

// ---- in-degree histogram over col ----
__global__ void k_deg(const void* __restrict__ edges) {
    int e = blockIdx.x * blockDim.x + threadIdx.x;
    if (e >= NE) return;
    int c = load_edge(edges, g_is64, (long long)NE + e);
    if ((unsigned)c < (unsigned)NN) atomicAdd(&g_cnt[c], 1);
}

// ---- blocked exclusive scan of cnt -> off ----
__global__ void k_scan1() {
    __shared__ int s[SCAN_CHUNK];
    int i = blockIdx.x * SCAN_CHUNK + threadIdx.x;
    int v = (i < NN) ? g_cnt[i] : 0;
    s[threadIdx.x] = v;
    __syncthreads();
    for (int d = 1; d < SCAN_CHUNK; d <<= 1) {
        int t = (threadIdx.x >= d) ? s[threadIdx.x - d] : 0;
        __syncthreads();
        s[threadIdx.x] += t;
        __syncthreads();
    }
    if (i < NN) g_off[i] = s[threadIdx.x] - v;
    if (threadIdx.x == SCAN_CHUNK - 1) g_bsum[blockIdx.x] = s[SCAN_CHUNK - 1];
}

__global__ void k_scan2() {
    __shared__ int s[128];
    int tid = threadIdx.x;
    int v = (tid < SCAN_NBLK) ? g_bsum[tid] : 0;
    s[tid] = v;
    __syncthreads();
    for (int d = 1; d < 128; d <<= 1) {
        int t = (tid >= d) ? s[tid - d] : 0;
        __syncthreads();
        s[tid] += t;
        __syncthreads();
    }
    if (tid < SCAN_NBLK) g_bsum[tid] = s[tid] - v;
}

// ---- scan fixup + dinv/d2 (fused) ----
__global__ void k_scan3() {
    int i = blockIdx.x * blockDim.x + threadIdx.x;
    if (i >= NN) return;
    g_off[i] += g_bsum[i / SCAN_CHUNK];
    float d = (float)(g_cnt[i] + 1);
    g_dinv[i] = 1.0f / sqrtf(d);
    g_d2[i]   = 1.0f / d;
}

// ---- place edges into CSC: single packed STG.64 per edge ----
__global__ void k_place(const void* __restrict__ edges) {
    int e = blockIdx.x * blockDim.x + threadIdx.x;
    if (e >= NE) return;
    int is64 = g_is64;
    int r = load_edge(edges, is64, e);
    int c = load_edge(edges, is64, (long long)NE + e);
    if ((unsigned)r >= (unsigned)NN) r = 0;
    if ((unsigned)c >= (unsigned)NN) c = 0;
    int p = atomicAdd(&g_cursor[c], 1);
    int2 rec;
    rec.x = r;
    rec.y = __float_as_int(g_dinv[r] * g_dinv[c]);
    g_adj[g_off[c] + p] = rec;
}

// ---- b = [x1|x2t] W4^T + b4 ; agg0 = x1 W1^T + b1 - bg ----
__global__ void k_ab(const float* __restrict__ x1, const float* __restrict__ x2,
                     const float* __restrict__ W4, const float* __restrict__ b4,
                     const float* __restrict__ W1, const float* __restrict__ b1,
                     const float* __restrict__ bg) {
    __shared__ float sW4[19 * 19], sb4[19], sW1[15 * 15], sb1[15], sbg[15];
    for (int i = threadIdx.x; i < 19 * 19; i += blockDim.x) sW4[i] = W4[i];
    for (int i = threadIdx.x; i < 15 * 15; i += blockDim.x) sW1[i] = W1[i];
    if (threadIdx.x < 19) sb4[threadIdx.x] = b4[threadIdx.x];
    if (threadIdx.x < 15) { sb1[threadIdx.x] = b1[threadIdx.x]; sbg[threadIdx.x] = bg[threadIdx.x]; }
    __syncthreads();

    int v = blockIdx.x * blockDim.x + threadIdx.x;
    if (v >= NN) return;

    float in[19];
    const float* x1r = x1 + (size_t)v * 15;
#pragma unroll
    for (int k = 0; k < 15; k++) in[k] = x1r[k];
    const float* x2r = x2 + (size_t)(v % NB) * 4;
#pragma unroll
    for (int k = 0; k < 4; k++) in[15 + k] = x2r[k];

    float* brow = g_b + (size_t)v * 19;
#pragma unroll
    for (int j = 0; j < 19; j++) {
        float acc = sb4[j];
#pragma unroll
        for (int k = 0; k < 19; k++) acc = fmaf(sW4[j * 19 + k], in[k], acc);
        brow[j] = acc;
    }

    float* arow = g_agg + (size_t)v * 16;
#pragma unroll
    for (int i = 0; i < 15; i++) {
        float acc = sb1[i] - sbg[i];
#pragma unroll
        for (int k = 0; k < 15; k++) acc = fmaf(sW1[i * 15 + k], in[k], acc);
        arow[i] = acc;
    }
    arow[15] = 0.0f;
}

// ---- kernel H: a = relu(agg+bg); h = Wg [a;b] ----
__global__ void k_H(const float* __restrict__ Wg, const float* __restrict__ bg) {
    __shared__ float sWg[15 * 34], sbg[15];
    for (int i = threadIdx.x; i < 15 * 34; i += blockDim.x) sWg[i] = Wg[i];
    if (threadIdx.x < 15) sbg[threadIdx.x] = bg[threadIdx.x];
    __syncthreads();

    int v = blockIdx.x * blockDim.x + threadIdx.x;
    if (v >= NN) return;

    float a[15], bb[19];
    const float* arow = g_agg + (size_t)v * 16;
#pragma unroll
    for (int i = 0; i < 15; i++) a[i] = fmaxf(arow[i] + sbg[i], 0.0f);
    const float* brow = g_b + (size_t)v * 19;
#pragma unroll
    for (int j = 0; j < 19; j++) bb[j] = brow[j];

    float* hrow = g_h + (size_t)v * 16;
#pragma unroll
    for (int o = 0; o < 15; o++) {
        float acc = 0.0f;
        const float* w = sWg + o * 34;
#pragma unroll
        for (int k = 0; k < 15; k++) acc = fmaf(w[k], a[k], acc);
#pragma unroll
        for (int k = 0; k < 19; k++) acc = fmaf(w[15 + k], bb[k], acc);
        hrow[o] = acc;
    }
    hrow[15] = 0.0f;
}

__device__ __forceinline__ float4 fma4(float4 p, float w, float4 a) {
    a.x = fmaf(p.x, w, a.x);
    a.y = fmaf(p.y, w, a.y);
    a.z = fmaf(p.z, w, a.z);
    a.w = fmaf(p.w, w, a.w);
    return a;
}

// ---- gather: 4 threads/node, float4 h rows, LDG.128 gathers (8 edges/warp/instr) ----
__global__ void k_gather() {
    int v = blockIdx.x * 64 + (threadIdx.x >> 2);   // 256 threads = 64 nodes/block
    int t = threadIdx.x & 3;                        // float4 quarter of the row
    if (v >= NN) return;

    int off = g_off[v];
    int cnt = g_cnt[v];
    const int2* __restrict__ ap = g_adj + off;
    const float4* __restrict__ h4 = reinterpret_cast<const float4*>(g_h);

    float d2 = g_d2[v];
    float4 acc = h4[(size_t)v * 4 + t];             // self loop
    acc.x *= d2; acc.y *= d2; acc.z *= d2; acc.w *= d2;
    float4 ac1 = make_float4(0.f, 0.f, 0.f, 0.f);

    int j = 0;
    for (; j + 4 <= cnt; j += 4) {
        int2 e0 = __ldg(ap + j + 0);
        int2 e1 = __ldg(ap + j + 1);
        int2 e2 = __ldg(ap + j + 2);
        int2 e3 = __ldg(ap + j + 3);
        float4 p0 = h4[(size_t)e0.x * 4 + t];
        float4 p1 = h4[(size_t)e1.x * 4 + t];
        float4 p2 = h4[(size_t)e2.x * 4 + t];
        float4 p3 = h4[(size_t)e3.x * 4 + t];
        acc = fma4(p0, __int_as_float(e0.y), acc);
        ac1 = fma4(p1, __int_as_float(e1.y), ac1);
        acc = fma4(p2, __int_as_float(e2.y), acc);
        ac1 = fma4(p3, __int_as_float(e3.y), ac1);
    }
    for (; j < cnt; j++) {
        int2 e = __ldg(ap + j);
        acc = fma4(h4[(size_t)e.x * 4 + t], __int_as_float(e.y), acc);
    }
    acc.x += ac1.x; acc.y += ac1.y; acc.z += ac1.z; acc.w += ac1.w;
    reinterpret_cast<float4*>(g_agg)[(size_t)v * 4 + t] = acc;   // coalesced STG.128
}

// ---- final: a = relu(agg+bg); sum_v W3 . [a;b] ----
__global__ void k_final(const float* __restrict__ W3, const float* __restrict__ bg) {
    __shared__ float sW3[34], sbg[15];
    __shared__ float warpsum[32];
    if (threadIdx.x < 34) sW3[threadIdx.x] = W3[threadIdx.x];
    if (threadIdx.x < 15) sbg[threadIdx.x] = bg[threadIdx.x];
    __syncthreads();

    int v = blockIdx.x * blockDim.x + threadIdx.x;
    float acc = 0.0f;
    if (v < NN) {
        const float* arow = g_agg + (size_t)v * 16;
#pragma unroll
        for (int i = 0; i < 15; i++) {
            float a = fmaxf(arow[i] + sbg[i], 0.0f);
            acc = fmaf(sW3[i], a, acc);
        }
        const float* brow = g_b + (size_t)v * 19;
#pragma unroll
        for (int j = 0; j < 19; j++) acc = fmaf(sW3[15 + j], brow[j], acc);
    }
#pragma unroll
    for (int off = 16; off > 0; off >>= 1)
        acc += __shfl_down_sync(0xFFFFFFFFu, acc, off);
    int lane = threadIdx.x & 31, wid = threadIdx.x >> 5;
    if (lane == 0) warpsum[wid] = acc;
    __syncthreads();
    if (wid == 0) {
        int nwarps = (blockDim.x + 31) >> 5;
        float s = (lane < nwarps) ? warpsum[lane] : 0.0f;
#pragma unroll
        for (int off = 16; off > 0; off >>= 1)
            s += __shfl_down_sync(0xFFFFFFFFu, s, off);
        if (lane == 0) atomicAdd(&g_sum, s);
    }
}

__global__ void k_out(const float* __restrict__ b3, float* __restrict__ out) {
    out[0] = tanhf(g_sum / (float)NN + b3[0]);
}

extern "C" void kernel_launch(void* const* d_in, const int* in_sizes, int n_in,
                              void* d_out, int out_size) {
    const float* x1    = (const float*)d_in[0];
    const float* x2    = (const float*)d_in[1];
    const void*  edges = d_in[2];
    const float* W1    = (const float*)d_in[3];
    const float* b1    = (const float*)d_in[4];
    const float* Wg    = (const float*)d_in[5];
    const float* bg    = (const float*)d_in[6];
    const float* W3    = (const float*)d_in[7];
    const float* b3    = (const float*)d_in[8];
    const float* W4    = (const float*)d_in[9];
    const float* b4    = (const float*)d_in[10];
    float* out = (float*)d_out;

    const int TB = 256;
    const int gN = (NN + TB - 1) / TB;
    const int gE = (NE + TB - 1) / TB;
    const int gG = (NN + 63) / 64;   // 4 threads/node, 64 nodes/block

    k_init<<<gN, TB>>>((const int*)edges);
    k_deg<<<gE, TB>>>(edges);
    k_scan1<<<SCAN_NBLK, SCAN_CHUNK>>>();
    k_scan2<<<1, 128>>>();
    k_scan3<<<gN, TB>>>();
    k_place<<<gE, TB>>>(edges);
    k_ab<<<gN, TB>>>(x1, x2, W4, b4, W1, b1, bg);
    for (int it = 0; it < 5; it++) {
        k_H<<<gN, TB>>>(Wg, bg);
        k_gather<<<gG, TB>>>();
    }
    k_final<<<gN, TB>>>(W3, bg);
    k_out<<<1, 1>>>(b3, out);
}